// round 8
// baseline (speedup 1.0000x reference)
#include <cuda_runtime.h>
#include <math.h>

#define Bc   64
#define Np   1024
#define Kn   20
#define Mf   256
#define NCc  40
#define EPSf 1e-5f

#define NB1  8192    // stats1 blocks  (B*N/8)
#define NB2  16384   // main blocks    (B*N/4)

// ---------------- scratch (static device memory only) ----------------
__device__ int    g_idx [Bc * Np * Kn];     // knn neighbor indices (local per cloud)
__device__ int    g_fidx[Bc * Mf];          // fps indices
__device__ float  g_part1[128 * NB1];       // per-block BN1 partial sum/sumsq
__device__ double g_stat1[128];
__device__ float  g_W2p[64 * 64];           // W2 with BN1 folded
__device__ float  g_b2p[64];
__device__ float  g_fmax[Bc * Np * 64];     // max over k of pre-BN2 relu
__device__ float  g_fmin[Bc * Np * 64];     // min over k
__device__ float  g_part2[128 * NB2];
__device__ double g_stat2[128];
__device__ float  g_s2v[64], g_t2v[64];     // BN2 scale / shift
__device__ float  g_ymax[Bc * 512];
__device__ float  g_ybn [Bc * 512];

// ---------------- kNN: top-20 smallest distances, self excluded ----------------
__global__ __launch_bounds__(256) void knn_kernel(const float* __restrict__ pos)
{
    int b   = blockIdx.x >> 2;         // cloud
    int seg = blockIdx.x & 3;          // query segment
    int tid = threadIdx.x;
    __shared__ float sx[Np], sy[Np], sz[Np], sn[Np];
    const float* p = pos + (size_t)b * Np * 3;
    for (int i = tid; i < Np; i += 256) {
        float x = p[3*i], y = p[3*i+1], z = p[3*i+2];
        sx[i] = x; sy[i] = y; sz[i] = z;
        sn[i] = (x*x + y*y) + z*z;
    }
    __syncthreads();

    int i = seg * 256 + tid;
    float xi = sx[i], yi = sy[i], zi = sz[i], ni = sn[i];

    float bd[Kn]; int bi[Kn];
#pragma unroll
    for (int t = 0; t < Kn; t++) { bd[t] = 3.4e38f; bi[t] = -1; }
    float curmax = 3.4e38f; int curslot = 0;

    for (int j = 0; j < Np; j++) {
        float dot = fmaf(xi, sx[j], fmaf(yi, sy[j], zi * sz[j]));
        float d   = (ni + sn[j]) - 2.0f * dot;
        if (j == i) continue;
        if (d < curmax) {                 // strict < keeps earlier (lower) index on ties
#pragma unroll
            for (int t = 0; t < Kn; t++) if (t == curslot) { bd[t] = d; bi[t] = j; }
            float m = -3.4e38f; int s = 0;
#pragma unroll
            for (int t = 0; t < Kn; t++) if (bd[t] > m) { m = bd[t]; s = t; }
            curmax = m; curslot = s;
        }
    }
    int base = (b * Np + i) * Kn;
#pragma unroll
    for (int t = 0; t < Kn; t++) g_idx[base + t] = bi[t];
}

// ---------------- FPS: must match reference fp32 bit-exactly ----------------
__global__ __launch_bounds__(256) void fps_kernel(const float* __restrict__ pos)
{
    int b = blockIdx.x, tid = threadIdx.x;
    __shared__ float sx[Np], sy[Np], sz[Np];
    __shared__ float wv[8]; __shared__ int wi[8];
    __shared__ int s_last;
    const float* p = pos + (size_t)b * Np * 3;
    for (int i = tid; i < Np; i += 256) { sx[i] = p[3*i]; sy[i] = p[3*i+1]; sz[i] = p[3*i+2]; }
    float dist[4];
#pragma unroll
    for (int q = 0; q < 4; q++) dist[q] = 1e38f;
    if (tid == 0) { g_fidx[b * Mf] = 0; s_last = 0; }
    __syncthreads();
    int last = 0;
    for (int step = 1; step < Mf; step++) {
        float lx = sx[last], ly = sy[last], lz = sz[last];
        float bv = -3.4e38f; int bix = 0x7fffffff;
#pragma unroll
        for (int q = 0; q < 4; q++) {
            int i = tid + q * 256;
            float dx = sx[i] - lx, dy = sy[i] - ly, dz = sz[i] - lz;
            // no-FMA, (x+y)+z order: matches jnp sum((p-q)**2, -1) exactly
            float dd = __fadd_rn(__fadd_rn(__fmul_rn(dx,dx), __fmul_rn(dy,dy)), __fmul_rn(dz,dz));
            float nd = fminf(dist[q], dd);
            dist[q] = nd;
            if (nd > bv || (nd == bv && i < bix)) { bv = nd; bix = i; }
        }
#pragma unroll
        for (int o = 16; o > 0; o >>= 1) {
            float ov = __shfl_down_sync(0xffffffffu, bv, o);
            int   oi = __shfl_down_sync(0xffffffffu, bix, o);
            if (ov > bv || (ov == bv && oi < bix)) { bv = ov; bix = oi; }
        }
        if ((tid & 31) == 0) { wv[tid >> 5] = bv; wi[tid >> 5] = bix; }
        __syncthreads();
        if (tid == 0) {
            float v = wv[0]; int ix = wi[0];
#pragma unroll
            for (int w = 1; w < 8; w++)
                if (wv[w] > v || (wv[w] == v && wi[w] < ix)) { v = wv[w]; ix = wi[w]; }
            g_fidx[b * Mf + step] = ix; s_last = ix;
        }
        __syncthreads();
        last = s_last;
    }
}

// ---------------- BN1 statistics over relu(rel @ W1^T + b1) ----------------
__global__ __launch_bounds__(256) void stats1_kernel(const float* __restrict__ pos,
                                                     const float* __restrict__ w1,
                                                     const float* __restrict__ b1)
{
    __shared__ float rel[160][4];
    __shared__ float ssum[64], ssq[64];
    int tid = threadIdx.x;
    int p0  = blockIdx.x * 8;
    if (tid < 64) { ssum[tid] = 0.f; ssq[tid] = 0.f; }
    if (tid < 160) {
        int gp = p0 + tid / 20, k = tid % 20;
        int b  = gp >> 10;
        int nb = (b << 10) + g_idx[gp * Kn + k];
        rel[tid][0] = pos[nb*3+0] - pos[gp*3+0];
        rel[tid][1] = pos[nb*3+1] - pos[gp*3+1];
        rel[tid][2] = pos[nb*3+2] - pos[gp*3+2];
    }
    int c = tid & 63;
    float w0 = w1[c*3], wv1 = w1[c*3+1], wv2 = w1[c*3+2], bb = b1[c];
    __syncthreads();
    int rg = tid >> 6;
    float ps = 0.f, pq = 0.f;
#pragma unroll 4
    for (int q = 0; q < 40; q++) {
        int r = rg * 40 + q;
        float h = fmaf(rel[r][0], w0, fmaf(rel[r][1], wv1, fmaf(rel[r][2], wv2, bb)));
        h = fmaxf(h, 0.f);
        ps += h; pq = fmaf(h, h, pq);
    }
    atomicAdd(&ssum[c], ps); atomicAdd(&ssq[c], pq);
    __syncthreads();
    if (tid < 64) {
        g_part1[tid * NB1 + blockIdx.x]        = ssum[tid];
        g_part1[(64 + tid) * NB1 + blockIdx.x] = ssq[tid];
    }
}

// ---------------- partial-sum reducers ----------------
__global__ void reduce1_kernel()
{
    __shared__ double red[256];
    int v = blockIdx.x, tid = threadIdx.x;
    double a = 0.0;
    for (int i = tid; i < NB1; i += 256) a += (double)g_part1[v * NB1 + i];
    red[tid] = a; __syncthreads();
    for (int o = 128; o > 0; o >>= 1) { if (tid < o) red[tid] += red[tid + o]; __syncthreads(); }
    if (tid == 0) g_stat1[v] = red[0];
}
__global__ void reduce2_kernel()
{
    __shared__ double red[256];
    int v = blockIdx.x, tid = threadIdx.x;
    double a = 0.0;
    for (int i = tid; i < NB2; i += 256) a += (double)g_part2[v * NB2 + i];
    red[tid] = a; __syncthreads();
    for (int o = 128; o > 0; o >>= 1) { if (tid < o) red[tid] += red[tid + o]; __syncthreads(); }
    if (tid == 0) g_stat2[v] = red[0];
}

// ---------------- fold BN1 into W2/b2 ----------------
__global__ __launch_bounds__(64) void fold1_kernel(const float* __restrict__ g1,
                                                   const float* __restrict__ be1,
                                                   const float* __restrict__ w2,
                                                   const float* __restrict__ b2)
{
    __shared__ float a1s[64], c1s[64];
    int t = threadIdx.x;
    const double CNT = (double)Bc * Np * Kn;          // 1310720
    double m = g_stat1[t] / CNT;
    double v = g_stat1[64 + t] / CNT - m * m;
    float af = g1[t] * (float)(1.0 / sqrt(v + (double)EPSf));
    a1s[t] = af;
    c1s[t] = be1[t] - (float)m * af;
    __syncthreads();
    float bb = b2[t];
    for (int f = 0; f < 64; f++) {
        float w = w2[t * 64 + f];
        g_W2p[t * 64 + f] = w * a1s[f];
        bb = fmaf(w, c1s[f], bb);
    }
    g_b2p[t] = bb;
}

// ---------------- main fused edge-MLP: h1 -> h2_pre, max/min over k, BN2 stats ----------------
__global__ __launch_bounds__(256) void main_kernel(const float* __restrict__ pos,
                                                   const float* __restrict__ w1,
                                                   const float* __restrict__ b1)
{
    __shared__ __align__(16) float h1s[80 * 65];
    __shared__ __align__(16) float w2s[64 * 64];      // [f][g]
    __shared__ float rel[80][4];
    __shared__ float b2s[64];
    __shared__ unsigned smax[256], smin[256];
    __shared__ float ssum[64], ssq[64];
    int tid = threadIdx.x;
#pragma unroll
    for (int t = 0; t < 16; t++) {
        int i = tid + t * 256;
        int g = i >> 6, f = i & 63;
        w2s[f * 64 + g] = g_W2p[i];
    }
    if (tid < 64) { b2s[tid] = g_b2p[tid]; ssum[tid] = 0.f; ssq[tid] = 0.f; }
    smax[tid] = 0u; smin[tid] = 0x7f800000u;
    int p0 = blockIdx.x * 4;
    if (tid < 80) {
        int gp = p0 + tid / 20, k = tid % 20;
        int b  = gp >> 10;
        int nb = (b << 10) + g_idx[gp * Kn + k];
        rel[tid][0] = pos[nb*3+0] - pos[gp*3+0];
        rel[tid][1] = pos[nb*3+1] - pos[gp*3+1];
        rel[tid][2] = pos[nb*3+2] - pos[gp*3+2];
    }
    __syncthreads();
    {   // h1 = relu(rel @ W1^T + b1)
        int c = tid & 63, rg = tid >> 6;
        float w0 = w1[c*3], wv1 = w1[c*3+1], wv2 = w1[c*3+2], bb = b1[c];
#pragma unroll 4
        for (int q = 0; q < 20; q++) {
            int r = rg * 20 + q;
            float h = fmaf(rel[r][0], w0, fmaf(rel[r][1], wv1, fmaf(rel[r][2], wv2, bb)));
            h1s[r * 65 + c] = fmaxf(h, 0.f);
        }
    }
    __syncthreads();
    // register-tiled 80x64 GEMM: thread tile 5 rows x 4 cols
    int cg = tid & 15, rg2 = tid >> 4;
    int r0 = rg2 * 5, c0 = cg * 4;
    float acc[5][4];
#pragma unroll
    for (int i = 0; i < 5; i++)
#pragma unroll
        for (int j = 0; j < 4; j++) acc[i][j] = 0.f;
#pragma unroll 8
    for (int f = 0; f < 64; f++) {
        float4 bv = *(const float4*)&w2s[(f << 6) + c0];
        int base = r0 * 65 + f;
        float a0 = h1s[base], a1 = h1s[base+65], a2 = h1s[base+130], a3 = h1s[base+195], a4 = h1s[base+260];
        acc[0][0]=fmaf(a0,bv.x,acc[0][0]); acc[0][1]=fmaf(a0,bv.y,acc[0][1]); acc[0][2]=fmaf(a0,bv.z,acc[0][2]); acc[0][3]=fmaf(a0,bv.w,acc[0][3]);
        acc[1][0]=fmaf(a1,bv.x,acc[1][0]); acc[1][1]=fmaf(a1,bv.y,acc[1][1]); acc[1][2]=fmaf(a1,bv.z,acc[1][2]); acc[1][3]=fmaf(a1,bv.w,acc[1][3]);
        acc[2][0]=fmaf(a2,bv.x,acc[2][0]); acc[2][1]=fmaf(a2,bv.y,acc[2][1]); acc[2][2]=fmaf(a2,bv.z,acc[2][2]); acc[2][3]=fmaf(a2,bv.w,acc[2][3]);
        acc[3][0]=fmaf(a3,bv.x,acc[3][0]); acc[3][1]=fmaf(a3,bv.y,acc[3][1]); acc[3][2]=fmaf(a3,bv.z,acc[3][2]); acc[3][3]=fmaf(a3,bv.w,acc[3][3]);
        acc[4][0]=fmaf(a4,bv.x,acc[4][0]); acc[4][1]=fmaf(a4,bv.y,acc[4][1]); acc[4][2]=fmaf(a4,bv.z,acc[4][2]); acc[4][3]=fmaf(a4,bv.w,acc[4][3]);
    }
    // epilogue: relu, local max/min over the 5 rows (one point), BN2 stats
    int pl = r0 / 20;
    float psum[4] = {0,0,0,0}, psq[4] = {0,0,0,0};
    float pmx[4], pmn[4];
#pragma unroll
    for (int j = 0; j < 4; j++) { pmx[j] = 0.f; pmn[j] = 3.4e38f; }
#pragma unroll
    for (int i = 0; i < 5; i++)
#pragma unroll
        for (int j = 0; j < 4; j++) {
            float v = fmaxf(acc[i][j] + b2s[c0 + j], 0.f);
            psum[j] += v; psq[j] = fmaf(v, v, psq[j]);
            pmx[j] = fmaxf(pmx[j], v); pmn[j] = fminf(pmn[j], v);
        }
#pragma unroll
    for (int j = 0; j < 4; j++) {
        atomicMax(&smax[pl * 64 + c0 + j], __float_as_uint(pmx[j]));   // values >= 0: uint order ok
        atomicMin(&smin[pl * 64 + c0 + j], __float_as_uint(pmn[j]));
        atomicAdd(&ssum[c0 + j], psum[j]);
        atomicAdd(&ssq[c0 + j], psq[j]);
    }
    __syncthreads();
    {
        int pp = tid >> 6, c = tid & 63;
        int gp = p0 + pp;
        g_fmax[gp * 64 + c] = __uint_as_float(smax[tid]);
        g_fmin[gp * 64 + c] = __uint_as_float(smin[tid]);
    }
    if (tid < 64) {
        g_part2[tid * NB2 + blockIdx.x]        = ssum[tid];
        g_part2[(64 + tid) * NB2 + blockIdx.x] = ssq[tid];
    }
}

// ---------------- BN2 scale/shift ----------------
__global__ __launch_bounds__(64) void bn2fold_kernel(const float* __restrict__ g2,
                                                     const float* __restrict__ be2)
{
    int c = threadIdx.x;
    const double CNT = (double)Bc * Np * Kn;
    double m = g_stat2[c] / CNT;
    double v = g_stat2[64 + c] / CNT - m * m;
    float sc = g2[c] * (float)(1.0 / sqrt(v + (double)EPSf));
    g_s2v[c] = sc;
    g_t2v[c] = be2[c] - (float)m * sc;
}

// ---------------- classifier: gather fps feats, [256,64]@[64,512], max over M ----------------
__global__ __launch_bounds__(128) void cls_kernel(const float* __restrict__ w_nn1,
                                                  const float* __restrict__ b_nn1)
{
    __shared__ __align__(16) float fs[32][64];
    __shared__ float s2s[64], t2s[64];
    int tid = threadIdx.x;
    int b = blockIdx.x >> 2, hc = blockIdx.x & 3;
    int h = hc * 128 + tid;
    if (tid < 64) { s2s[tid] = g_s2v[tid]; t2s[tid] = g_t2v[tid]; }
    __syncthreads();
    float wr[64]; float beff = b_nn1[h];
#pragma unroll
    for (int c = 0; c < 64; c++) {
        float w = w_nn1[h * 64 + c];
        wr[c] = w * s2s[c];
        beff = fmaf(w, t2s[c], beff);
    }
    float ymax = -3.4e38f;
    for (int mt = 0; mt < 8; mt++) {
        __syncthreads();
#pragma unroll
        for (int t = 0; t < 16; t++) {
            int l = tid + t * 128;
            int m = l >> 6, c = l & 63;
            int gi = g_fidx[b * Mf + mt * 32 + m];
            int gp = b * Np + gi;
            fs[m][c] = (s2s[c] > 0.f) ? g_fmax[gp * 64 + c] : g_fmin[gp * 64 + c];
        }
        __syncthreads();
        for (int m = 0; m < 32; m++) {
            float acc = beff;
#pragma unroll
            for (int c4 = 0; c4 < 16; c4++) {
                float4 fv = *(const float4*)&fs[m][c4 * 4];
                acc = fmaf(fv.x, wr[c4*4+0], acc);
                acc = fmaf(fv.y, wr[c4*4+1], acc);
                acc = fmaf(fv.z, wr[c4*4+2], acc);
                acc = fmaf(fv.w, wr[c4*4+3], acc);
            }
            ymax = fmaxf(ymax, acc);
        }
    }
    g_ymax[b * 512 + h] = ymax;
}

// ---------------- head: relu + BN over batch ----------------
__global__ __launch_bounds__(128) void head_kernel(const float* __restrict__ gg,
                                                   const float* __restrict__ bb)
{
    int h = blockIdx.x * 128 + threadIdx.x;
    float s = 0.f, q = 0.f;
    for (int b = 0; b < Bc; b++) {
        float y = fmaxf(g_ymax[b * 512 + h], 0.f);
        s += y; q = fmaf(y, y, q);
    }
    float m  = s / 64.f;
    float v  = q / 64.f - m * m;
    float sc = gg[h] * rsqrtf(v + EPSf);
    float tt = bb[h] - m * sc;
    for (int b = 0; b < Bc; b++) {
        float y = fmaxf(g_ymax[b * 512 + h], 0.f);
        g_ybn[b * 512 + h] = fmaf(y, sc, tt);
    }
}

// ---------------- final linear + log_softmax ----------------
__global__ __launch_bounds__(64) void final_kernel(const float* __restrict__ w4,
                                                   const float* __restrict__ b4,
                                                   float* __restrict__ out)
{
    __shared__ float yr[512];
    __shared__ float lg[40];
    __shared__ float s_mx, s_lse;
    int b = blockIdx.x, tid = threadIdx.x;
#pragma unroll
    for (int t = 0; t < 8; t++) yr[tid + t * 64] = g_ybn[b * 512 + tid + t * 64];
    __syncthreads();
    if (tid < 40) {
        float acc = b4[tid];
        for (int c = 0; c < 512; c++) acc = fmaf(yr[c], w4[tid * 512 + c], acc);
        lg[tid] = acc;
    }
    __syncthreads();
    if (tid == 0) {
        float mx = -3.4e38f;
        for (int j = 0; j < 40; j++) mx = fmaxf(mx, lg[j]);
        float se = 0.f;
        for (int j = 0; j < 40; j++) se += expf(lg[j] - mx);
        s_mx = mx; s_lse = logf(se);
    }
    __syncthreads();
    if (tid < 40) out[b * 40 + tid] = lg[tid] - s_mx - s_lse;
}

// ---------------- launch ----------------
extern "C" void kernel_launch(void* const* d_in, const int* in_sizes, int n_in,
                              void* d_out, int out_size)
{
    const float* pos    = (const float*)d_in[0];
    const float* w1     = (const float*)d_in[1];
    const float* b1     = (const float*)d_in[2];
    const float* g1     = (const float*)d_in[3];
    const float* be1    = (const float*)d_in[4];
    const float* w2     = (const float*)d_in[5];
    const float* b2     = (const float*)d_in[6];
    const float* g2     = (const float*)d_in[7];
    const float* be2    = (const float*)d_in[8];
    const float* w_nn1  = (const float*)d_in[9];
    const float* b_nn1  = (const float*)d_in[10];
    const float* g_bn2  = (const float*)d_in[11];
    const float* be_bn2 = (const float*)d_in[12];
    const float* w_nn4  = (const float*)d_in[13];
    const float* b_nn4  = (const float*)d_in[14];
    float* out = (float*)d_out;

    knn_kernel   <<<256,   256>>>(pos);
    fps_kernel   <<<Bc,    256>>>(pos);
    stats1_kernel<<<NB1,   256>>>(pos, w1, b1);
    reduce1_kernel<<<128,  256>>>();
    fold1_kernel <<<1,      64>>>(g1, be1, w2, b2);
    main_kernel  <<<NB2,   256>>>(pos, w1, b1);
    reduce2_kernel<<<128,  256>>>();
    bn2fold_kernel<<<1,     64>>>(g2, be2);
    cls_kernel   <<<256,   128>>>(w_nn1, b_nn1);
    head_kernel  <<<4,     128>>>(g_bn2, be_bn2);
    final_kernel <<<Bc,     64>>>(w_nn4, b_nn4, out);
}

// round 9
// speedup vs baseline: 1.4142x; 1.4142x over previous
#include <cuda_runtime.h>
#include <math.h>

#define Bc   64
#define Np   1024
#define Kn   20
#define Mf   256
#define NCc  40
#define EPSf 1e-5f

#define NB1  8192    // stats1 blocks  (B*N/8)
#define NB2  16384   // main blocks    (B*N/4)

// ---------------- scratch (static device memory only) ----------------
__device__ int    g_idx [Bc * Np * Kn];     // knn neighbor indices (local per cloud)
__device__ int    g_fidx[Bc * Mf];          // fps indices
__device__ float  g_part1[128 * NB1];       // per-block BN1 partial sum/sumsq
__device__ double g_stat1[128];
__device__ float  g_W2p[64 * 64];           // W2 with BN1 folded
__device__ float  g_b2p[64];
__device__ float  g_fmax[Bc * Np * 64];     // max over k of pre-BN2 relu
__device__ float  g_fmin[Bc * Np * 64];     // min over k
__device__ float  g_part2[128 * NB2];
__device__ double g_stat2[128];
__device__ float  g_s2v[64], g_t2v[64];     // BN2 scale / shift
__device__ float  g_ymax[Bc * 512];
__device__ float  g_ybn [Bc * 512];

// ---------------- f32x2 packed helpers ----------------
__device__ __forceinline__ unsigned long long pk2(float lo, float hi) {
    unsigned long long r;
    asm("mov.b64 %0, {%1,%2};" : "=l"(r) : "r"(__float_as_uint(lo)), "r"(__float_as_uint(hi)));
    return r;
}
__device__ __forceinline__ void upk2(unsigned long long v, float& lo, float& hi) {
    unsigned a, b;
    asm("mov.b64 {%0,%1}, %2;" : "=r"(a), "=r"(b) : "l"(v));
    lo = __uint_as_float(a); hi = __uint_as_float(b);
}
__device__ __forceinline__ unsigned long long ff2(unsigned long long a, unsigned long long b,
                                                  unsigned long long c) {
    unsigned long long d;
    asm("fma.rn.f32x2 %0, %1, %2, %3;" : "=l"(d) : "l"(a), "l"(b), "l"(c));
    return d;
}

// ---------------- kNN: value-only sorted top-20, then index recovery ----------------
__global__ __launch_bounds__(256) void knn_kernel(const float* __restrict__ pos)
{
    int b   = blockIdx.x >> 2;
    int seg = blockIdx.x & 3;
    int tid = threadIdx.x;
    __shared__ float sx[Np], sy[Np], sz[Np];
    const float* p = pos + (size_t)b * Np * 3;
    for (int i = tid; i < Np; i += 256) { sx[i] = p[3*i]; sy[i] = p[3*i+1]; sz[i] = p[3*i+2]; }
    __syncthreads();

    int i = seg * 256 + tid;
    float xi = sx[i], yi = sy[i], zi = sz[i];
    const float INFf = __int_as_float(0x7f800000);

    float bd[Kn];                 // descending: bd[0] = largest kept (20th smallest)
#pragma unroll
    for (int t = 0; t < Kn; t++) bd[t] = INFf;

    // pass 1: values only (no indices) — cheap FMNMX shift-insert
    for (int j = 0; j < Np; j++) {
        float dx = xi - sx[j], dy = yi - sy[j], dz = zi - sz[j];
        float d = fmaf(dx, dx, fmaf(dy, dy, dz * dz));
        if (j == i) d = INFf;
        if (d < bd[0]) {
#pragma unroll
            for (int t = 0; t < Kn - 1; t++) bd[t] = fmaxf(bd[t + 1], fminf(bd[t], d));
            bd[Kn - 1] = fminf(bd[Kn - 1], d);
        }
    }

    // pass 2: recover indices; ascending scan + count cap == stable top_k tie semantics
    float bound = bd[0];
    int base = (b * Np + i) * Kn;
    int cnt = 0;
    for (int j = 0; j < Np && cnt < Kn; j++) {
        if (j == i) continue;
        float dx = xi - sx[j], dy = yi - sy[j], dz = zi - sz[j];
        float d = fmaf(dx, dx, fmaf(dy, dy, dz * dz));
        if (d <= bound) { g_idx[base + cnt] = j; cnt++; }
    }
}

// ---------------- FPS: must match reference fp32 bit-exactly ----------------
__global__ __launch_bounds__(256) void fps_kernel(const float* __restrict__ pos)
{
    int b = blockIdx.x, tid = threadIdx.x;
    __shared__ float sx[Np], sy[Np], sz[Np];
    __shared__ float wv[8]; __shared__ int wi[8];
    __shared__ int s_last;
    const float* p = pos + (size_t)b * Np * 3;
    for (int i = tid; i < Np; i += 256) { sx[i] = p[3*i]; sy[i] = p[3*i+1]; sz[i] = p[3*i+2]; }
    float dist[4];
#pragma unroll
    for (int q = 0; q < 4; q++) dist[q] = 1e38f;
    if (tid == 0) { g_fidx[b * Mf] = 0; s_last = 0; }
    __syncthreads();
    int last = 0;
    for (int step = 1; step < Mf; step++) {
        float lx = sx[last], ly = sy[last], lz = sz[last];
        float bv = -3.4e38f; int bix = 0x7fffffff;
#pragma unroll
        for (int q = 0; q < 4; q++) {
            int i = tid + q * 256;
            float dx = sx[i] - lx, dy = sy[i] - ly, dz = sz[i] - lz;
            float dd = __fadd_rn(__fadd_rn(__fmul_rn(dx,dx), __fmul_rn(dy,dy)), __fmul_rn(dz,dz));
            float nd = fminf(dist[q], dd);
            dist[q] = nd;
            if (nd > bv || (nd == bv && i < bix)) { bv = nd; bix = i; }
        }
#pragma unroll
        for (int o = 16; o > 0; o >>= 1) {
            float ov = __shfl_down_sync(0xffffffffu, bv, o);
            int   oi = __shfl_down_sync(0xffffffffu, bix, o);
            if (ov > bv || (ov == bv && oi < bix)) { bv = ov; bix = oi; }
        }
        if ((tid & 31) == 0) { wv[tid >> 5] = bv; wi[tid >> 5] = bix; }
        __syncthreads();
        if (tid == 0) {
            float v = wv[0]; int ix = wi[0];
#pragma unroll
            for (int w = 1; w < 8; w++)
                if (wv[w] > v || (wv[w] == v && wi[w] < ix)) { v = wv[w]; ix = wi[w]; }
            g_fidx[b * Mf + step] = ix; s_last = ix;
        }
        __syncthreads();
        last = s_last;
    }
}

// ---------------- BN1 statistics over relu(rel @ W1^T + b1) ----------------
__global__ __launch_bounds__(256) void stats1_kernel(const float* __restrict__ pos,
                                                     const float* __restrict__ w1,
                                                     const float* __restrict__ b1)
{
    __shared__ float rel[160][4];
    __shared__ float ssum[64], ssq[64];
    int tid = threadIdx.x;
    int p0  = blockIdx.x * 8;
    if (tid < 64) { ssum[tid] = 0.f; ssq[tid] = 0.f; }
    if (tid < 160) {
        int gp = p0 + tid / 20, k = tid % 20;
        int b  = gp >> 10;
        int nb = (b << 10) + g_idx[gp * Kn + k];
        rel[tid][0] = pos[nb*3+0] - pos[gp*3+0];
        rel[tid][1] = pos[nb*3+1] - pos[gp*3+1];
        rel[tid][2] = pos[nb*3+2] - pos[gp*3+2];
    }
    int c = tid & 63;
    float w0 = w1[c*3], wv1 = w1[c*3+1], wv2 = w1[c*3+2], bb = b1[c];
    __syncthreads();
    int rg = tid >> 6;
    float ps = 0.f, pq = 0.f;
#pragma unroll 4
    for (int q = 0; q < 40; q++) {
        int r = rg * 40 + q;
        float h = fmaf(rel[r][0], w0, fmaf(rel[r][1], wv1, fmaf(rel[r][2], wv2, bb)));
        h = fmaxf(h, 0.f);
        ps += h; pq = fmaf(h, h, pq);
    }
    // 4 threads per channel (rg 0..3) -> merge via shared atomics (cheap here: 2/thread)
    atomicAdd(&ssum[c], ps); atomicAdd(&ssq[c], pq);
    __syncthreads();
    if (tid < 64) {
        g_part1[tid * NB1 + blockIdx.x]        = ssum[tid];
        g_part1[(64 + tid) * NB1 + blockIdx.x] = ssq[tid];
    }
}

// ---------------- partial-sum reducers ----------------
__global__ void reduce1_kernel()
{
    __shared__ double red[256];
    int v = blockIdx.x, tid = threadIdx.x;
    double a = 0.0;
    for (int i = tid; i < NB1; i += 256) a += (double)g_part1[v * NB1 + i];
    red[tid] = a; __syncthreads();
    for (int o = 128; o > 0; o >>= 1) { if (tid < o) red[tid] += red[tid + o]; __syncthreads(); }
    if (tid == 0) g_stat1[v] = red[0];
}
__global__ void reduce2_kernel()
{
    __shared__ double red[256];
    int v = blockIdx.x, tid = threadIdx.x;
    double a = 0.0;
    for (int i = tid; i < NB2; i += 256) a += (double)g_part2[v * NB2 + i];
    red[tid] = a; __syncthreads();
    for (int o = 128; o > 0; o >>= 1) { if (tid < o) red[tid] += red[tid + o]; __syncthreads(); }
    if (tid == 0) g_stat2[v] = red[0];
}

// ---------------- fold BN1 into W2/b2 ----------------
__global__ __launch_bounds__(64) void fold1_kernel(const float* __restrict__ g1,
                                                   const float* __restrict__ be1,
                                                   const float* __restrict__ w2,
                                                   const float* __restrict__ b2)
{
    __shared__ float a1s[64], c1s[64];
    int t = threadIdx.x;
    const double CNT = (double)Bc * Np * Kn;
    double m = g_stat1[t] / CNT;
    double v = g_stat1[64 + t] / CNT - m * m;
    float af = g1[t] * (float)(1.0 / sqrt(v + (double)EPSf));
    a1s[t] = af;
    c1s[t] = be1[t] - (float)m * af;
    __syncthreads();
    float bb = b2[t];
    for (int f = 0; f < 64; f++) {
        float w = w2[t * 64 + f];
        g_W2p[t * 64 + f] = w * a1s[f];
        bb = fmaf(w, c1s[f], bb);
    }
    g_b2p[t] = bb;
}

// ---------------- main fused edge-MLP (FFMA2 + shfl epilogue, no atomics) ----------------
__global__ __launch_bounds__(256) void main_kernel(const float* __restrict__ pos,
                                                   const float* __restrict__ w1,
                                                   const float* __restrict__ b1)
{
    __shared__ __align__(16) float h1s[80 * 65];
    __shared__ __align__(16) float w2s[64 * 64];      // [f][g]
    __shared__ float rel[80][4];
    __shared__ float b2s[64];
    int tid = threadIdx.x;
#pragma unroll
    for (int t = 0; t < 16; t++) {
        int i = tid + t * 256;
        int g = i >> 6, f = i & 63;
        w2s[f * 64 + g] = g_W2p[i];
    }
    if (tid < 64) b2s[tid] = g_b2p[tid];
    int p0 = blockIdx.x * 4;
    if (tid < 80) {
        int gp = p0 + tid / 20, k = tid % 20;
        int b  = gp >> 10;
        int nb = (b << 10) + g_idx[gp * Kn + k];
        rel[tid][0] = pos[nb*3+0] - pos[gp*3+0];
        rel[tid][1] = pos[nb*3+1] - pos[gp*3+1];
        rel[tid][2] = pos[nb*3+2] - pos[gp*3+2];
    }
    __syncthreads();
    {   // h1 = relu(rel @ W1^T + b1)
        int c = tid & 63, rg = tid >> 6;
        float w0 = w1[c*3], wv1 = w1[c*3+1], wv2 = w1[c*3+2], bb = b1[c];
#pragma unroll 4
        for (int q = 0; q < 20; q++) {
            int r = rg * 20 + q;
            float h = fmaf(rel[r][0], w0, fmaf(rel[r][1], wv1, fmaf(rel[r][2], wv2, bb)));
            h1s[r * 65 + c] = fmaxf(h, 0.f);
        }
    }
    __syncthreads();
    // thread mapping: cg = tid>>4 (columns), rg2 = tid&15 (rows) so the 4 threads
    // sharing a point (rg2 quad) are adjacent lanes -> shfl merge, no atomics.
    int cg = tid >> 4, rg2 = tid & 15;
    int r0 = rg2 * 5, c0 = cg * 4;
    unsigned long long a01[5], a23[5];
#pragma unroll
    for (int i = 0; i < 5; i++) { a01[i] = 0ull; a23[i] = 0ull; }
#pragma unroll 8
    for (int f = 0; f < 64; f++) {
        ulonglong2 bvp = *(const ulonglong2*)&w2s[(f << 6) + c0];
        int base = r0 * 65 + f;
#pragma unroll
        for (int i = 0; i < 5; i++) {
            float a = h1s[base + 65 * i];
            unsigned long long aa = pk2(a, a);
            a01[i] = ff2(aa, bvp.x, a01[i]);
            a23[i] = ff2(aa, bvp.y, a23[i]);
        }
    }
    // epilogue: relu, per-point max/min, block-wide per-channel sum/sumsq via shfl
    float bb0 = b2s[c0], bb1 = b2s[c0+1], bb2 = b2s[c0+2], bb3 = b2s[c0+3];
    float psum[4] = {0,0,0,0}, psq[4] = {0,0,0,0};
    float pmx[4], pmn[4];
#pragma unroll
    for (int j = 0; j < 4; j++) { pmx[j] = 0.f; pmn[j] = 3.4e38f; }
#pragma unroll
    for (int i = 0; i < 5; i++) {
        float v[4];
        upk2(a01[i], v[0], v[1]);
        upk2(a23[i], v[2], v[3]);
        v[0] = fmaxf(v[0] + bb0, 0.f); v[1] = fmaxf(v[1] + bb1, 0.f);
        v[2] = fmaxf(v[2] + bb2, 0.f); v[3] = fmaxf(v[3] + bb3, 0.f);
#pragma unroll
        for (int j = 0; j < 4; j++) {
            psum[j] += v[j]; psq[j] = fmaf(v[j], v[j], psq[j]);
            pmx[j] = fmaxf(pmx[j], v[j]); pmn[j] = fminf(pmn[j], v[j]);
        }
    }
    const unsigned FULL = 0xffffffffu;
#pragma unroll
    for (int o = 1; o <= 2; o <<= 1)
#pragma unroll
        for (int j = 0; j < 4; j++) {
            pmx[j] = fmaxf(pmx[j], __shfl_xor_sync(FULL, pmx[j], o));
            pmn[j] = fminf(pmn[j], __shfl_xor_sync(FULL, pmn[j], o));
        }
#pragma unroll
    for (int o = 1; o <= 8; o <<= 1)
#pragma unroll
        for (int j = 0; j < 4; j++) {
            psum[j] += __shfl_xor_sync(FULL, psum[j], o);
            psq[j]  += __shfl_xor_sync(FULL, psq[j],  o);
        }
    if ((tid & 3) == 0) {
        int pl = (tid >> 2) & 3;
        int gp = p0 + pl;
        *(float4*)&g_fmax[gp * 64 + c0] = make_float4(pmx[0], pmx[1], pmx[2], pmx[3]);
        *(float4*)&g_fmin[gp * 64 + c0] = make_float4(pmn[0], pmn[1], pmn[2], pmn[3]);
    }
    if ((tid & 15) == 0) {
#pragma unroll
        for (int j = 0; j < 4; j++) {
            g_part2[(c0 + j) * NB2 + blockIdx.x]      = psum[j];
            g_part2[(64 + c0 + j) * NB2 + blockIdx.x] = psq[j];
        }
    }
}

// ---------------- BN2 scale/shift ----------------
__global__ __launch_bounds__(64) void bn2fold_kernel(const float* __restrict__ g2,
                                                     const float* __restrict__ be2)
{
    int c = threadIdx.x;
    const double CNT = (double)Bc * Np * Kn;
    double m = g_stat2[c] / CNT;
    double v = g_stat2[64 + c] / CNT - m * m;
    float sc = g2[c] * (float)(1.0 / sqrt(v + (double)EPSf));
    g_s2v[c] = sc;
    g_t2v[c] = be2[c] - (float)m * sc;
}

// ---------------- classifier: gather fps feats, [256,64]@[64,512], max over M ----------------
__global__ __launch_bounds__(128) void cls_kernel(const float* __restrict__ w_nn1,
                                                  const float* __restrict__ b_nn1)
{
    __shared__ __align__(16) float fs[32][64];
    __shared__ float s2s[64], t2s[64];
    int tid = threadIdx.x;
    int b = blockIdx.x >> 2, hc = blockIdx.x & 3;
    int h = hc * 128 + tid;
    if (tid < 64) { s2s[tid] = g_s2v[tid]; t2s[tid] = g_t2v[tid]; }
    __syncthreads();
    unsigned long long wrp[32];
    float beff = b_nn1[h];
#pragma unroll
    for (int c2 = 0; c2 < 32; c2++) {
        float wa = w_nn1[h * 64 + 2*c2], wb = w_nn1[h * 64 + 2*c2 + 1];
        beff = fmaf(wa, t2s[2*c2], beff);
        beff = fmaf(wb, t2s[2*c2 + 1], beff);
        wrp[c2] = pk2(wa * s2s[2*c2], wb * s2s[2*c2 + 1]);
    }
    float ymax = -3.4e38f;
    for (int mt = 0; mt < 8; mt++) {
        __syncthreads();
#pragma unroll
        for (int t = 0; t < 16; t++) {
            int l = tid + t * 128;
            int m = l >> 6, c = l & 63;
            int gi = g_fidx[b * Mf + mt * 32 + m];
            int gp = b * Np + gi;
            fs[m][c] = (s2s[c] > 0.f) ? g_fmax[gp * 64 + c] : g_fmin[gp * 64 + c];
        }
        __syncthreads();
        for (int m = 0; m < 32; m++) {
            unsigned long long acc = 0ull;
#pragma unroll
            for (int c4 = 0; c4 < 16; c4++) {
                ulonglong2 fv = *(const ulonglong2*)&fs[m][c4 * 4];
                acc = ff2(fv.x, wrp[2 * c4],     acc);
                acc = ff2(fv.y, wrp[2 * c4 + 1], acc);
            }
            float al, ah; upk2(acc, al, ah);
            ymax = fmaxf(ymax, (beff + al) + ah);
        }
    }
    g_ymax[b * 512 + h] = ymax;
}

// ---------------- head: relu + BN over batch ----------------
__global__ __launch_bounds__(128) void head_kernel(const float* __restrict__ gg,
                                                   const float* __restrict__ bb)
{
    int h = blockIdx.x * 128 + threadIdx.x;
    float s = 0.f, q = 0.f;
    for (int b = 0; b < Bc; b++) {
        float y = fmaxf(g_ymax[b * 512 + h], 0.f);
        s += y; q = fmaf(y, y, q);
    }
    float m  = s / 64.f;
    float v  = q / 64.f - m * m;
    float sc = gg[h] * rsqrtf(v + EPSf);
    float tt = bb[h] - m * sc;
    for (int b = 0; b < Bc; b++) {
        float y = fmaxf(g_ymax[b * 512 + h], 0.f);
        g_ybn[b * 512 + h] = fmaf(y, sc, tt);
    }
}

// ---------------- final linear + log_softmax ----------------
__global__ __launch_bounds__(64) void final_kernel(const float* __restrict__ w4,
                                                   const float* __restrict__ b4,
                                                   float* __restrict__ out)
{
    __shared__ float yr[512];
    __shared__ float lg[40];
    __shared__ float s_mx, s_lse;
    int b = blockIdx.x, tid = threadIdx.x;
#pragma unroll
    for (int t = 0; t < 8; t++) yr[tid + t * 64] = g_ybn[b * 512 + tid + t * 64];
    __syncthreads();
    if (tid < 40) {
        float acc = b4[tid];
        for (int c = 0; c < 512; c++) acc = fmaf(yr[c], w4[tid * 512 + c], acc);
        lg[tid] = acc;
    }
    __syncthreads();
    if (tid == 0) {
        float mx = -3.4e38f;
        for (int j = 0; j < 40; j++) mx = fmaxf(mx, lg[j]);
        float se = 0.f;
        for (int j = 0; j < 40; j++) se += expf(lg[j] - mx);
        s_mx = mx; s_lse = logf(se);
    }
    __syncthreads();
    if (tid < 40) out[b * 40 + tid] = lg[tid] - s_mx - s_lse;
}

// ---------------- launch ----------------
extern "C" void kernel_launch(void* const* d_in, const int* in_sizes, int n_in,
                              void* d_out, int out_size)
{
    const float* pos    = (const float*)d_in[0];
    const float* w1     = (const float*)d_in[1];
    const float* b1     = (const float*)d_in[2];
    const float* g1     = (const float*)d_in[3];
    const float* be1    = (const float*)d_in[4];
    const float* w2     = (const float*)d_in[5];
    const float* b2     = (const float*)d_in[6];
    const float* g2     = (const float*)d_in[7];
    const float* be2    = (const float*)d_in[8];
    const float* w_nn1  = (const float*)d_in[9];
    const float* b_nn1  = (const float*)d_in[10];
    const float* g_bn2  = (const float*)d_in[11];
    const float* be_bn2 = (const float*)d_in[12];
    const float* w_nn4  = (const float*)d_in[13];
    const float* b_nn4  = (const float*)d_in[14];
    float* out = (float*)d_out;

    knn_kernel   <<<256,   256>>>(pos);
    fps_kernel   <<<Bc,    256>>>(pos);
    stats1_kernel<<<NB1,   256>>>(pos, w1, b1);
    reduce1_kernel<<<128,  256>>>();
    fold1_kernel <<<1,      64>>>(g1, be1, w2, b2);
    main_kernel  <<<NB2,   256>>>(pos, w1, b1);
    reduce2_kernel<<<128,  256>>>();
    bn2fold_kernel<<<1,     64>>>(g2, be2);
    cls_kernel   <<<256,   128>>>(w_nn1, b_nn1);
    head_kernel  <<<4,     128>>>(g_bn2, be_bn2);
    final_kernel <<<Bc,     64>>>(w_nn4, b_nn4, out);
}

// round 10
// speedup vs baseline: 1.5615x; 1.1042x over previous
#include <cuda_runtime.h>
#include <math.h>

#define Bc   64
#define Np   1024
#define Kn   20
#define Mf   256
#define NCc  40
#define EPSf 1e-5f

#define NB1  8192    // stats1 blocks  (B*N/8)
#define NB2  16384   // main blocks    (B*N/4)

// ---------------- scratch (static device memory only) ----------------
__device__ int    g_idx [Bc * Np * Kn];
__device__ int    g_fidx[Bc * Mf];
__device__ float  g_part1[128 * NB1];
__device__ double g_p1b[128 * 4];
__device__ float  g_W2p[64 * 64];
__device__ float  g_b2p[64];
__device__ float  g_fmax[Bc * Np * 64];
__device__ float  g_fmin[Bc * Np * 64];
__device__ float  g_part2[128 * NB2];
__device__ double g_p2b[128 * 8];
__device__ float  g_s2v[64], g_t2v[64];
__device__ float  g_ymax[Bc * 512];
__device__ float  g_ybn [Bc * 512];

// ---------------- f32x2 packed helpers ----------------
__device__ __forceinline__ unsigned long long pk2(float lo, float hi) {
    unsigned long long r;
    asm("mov.b64 %0, {%1,%2};" : "=l"(r) : "r"(__float_as_uint(lo)), "r"(__float_as_uint(hi)));
    return r;
}
__device__ __forceinline__ void upk2(unsigned long long v, float& lo, float& hi) {
    unsigned a, b;
    asm("mov.b64 {%0,%1}, %2;" : "=r"(a), "=r"(b) : "l"(v));
    lo = __uint_as_float(a); hi = __uint_as_float(b);
}
__device__ __forceinline__ unsigned long long ff2(unsigned long long a, unsigned long long b,
                                                  unsigned long long c) {
    unsigned long long d;
    asm("fma.rn.f32x2 %0, %1, %2, %3;" : "=l"(d) : "l"(a), "l"(b), "l"(c));
    return d;
}
__device__ __forceinline__ unsigned long long add2(unsigned long long a, unsigned long long b) {
    unsigned long long d;
    asm("add.rn.f32x2 %0, %1, %2;" : "=l"(d) : "l"(a), "l"(b));
    return d;
}
__device__ __forceinline__ unsigned long long mul2(unsigned long long a, unsigned long long b) {
    unsigned long long d;
    asm("mul.rn.f32x2 %0, %1, %2;" : "=l"(d) : "l"(a), "l"(b));
    return d;
}

// ---------------- kNN: 21-slot value list (self incl.), packed distances ----------------
__global__ __launch_bounds__(256) void knn_kernel(const float* __restrict__ pos)
{
    int b   = blockIdx.x >> 2;
    int seg = blockIdx.x & 3;
    int tid = threadIdx.x;
    __shared__ __align__(16) float snx[Np], sny[Np], snz[Np];   // negated coords
    const float* p = pos + (size_t)b * Np * 3;
    for (int i = tid; i < Np; i += 256) {
        snx[i] = -p[3*i]; sny[i] = -p[3*i+1]; snz[i] = -p[3*i+2];
    }
    __syncthreads();

    int i = seg * 256 + tid;
    float xi = -snx[i], yi = -sny[i], zi = -snz[i];
    unsigned long long xi2 = pk2(xi, xi), yi2 = pk2(yi, yi), zi2 = pk2(zi, zi);
    const float INFf = __int_as_float(0x7f800000);

    float bd[Kn + 1];                 // 21 slots; bd[0] = 21st smallest incl. self
#pragma unroll
    for (int t = 0; t <= Kn; t++) bd[t] = INFf;

#pragma unroll 4
    for (int j = 0; j < Np; j += 2) {
        unsigned long long nx = *(const unsigned long long*)&snx[j];
        unsigned long long ny = *(const unsigned long long*)&sny[j];
        unsigned long long nz = *(const unsigned long long*)&snz[j];
        unsigned long long dx = add2(xi2, nx);
        unsigned long long dy = add2(yi2, ny);
        unsigned long long dz = add2(zi2, nz);
        unsigned long long dp = ff2(dx, dx, ff2(dy, dy, mul2(dz, dz)));
        float d0, d1; upk2(dp, d0, d1);
        if (d0 < bd[0]) {
#pragma unroll
            for (int t = 0; t < Kn; t++) bd[t] = fmaxf(bd[t + 1], fminf(bd[t], d0));
            bd[Kn] = fminf(bd[Kn], d0);
        }
        if (d1 < bd[0]) {
#pragma unroll
            for (int t = 0; t < Kn; t++) bd[t] = fmaxf(bd[t + 1], fminf(bd[t], d1));
            bd[Kn] = fminf(bd[Kn], d1);
        }
    }

    // pass 2: recover indices (self excluded); identical arithmetic to pass 1
    float bound = bd[0];
    int base = (b * Np + i) * Kn;
    int cnt = 0;
    for (int j = 0; j < Np && cnt < Kn; j++) {
        if (j == i) continue;
        float dx = xi + snx[j], dy = yi + sny[j], dz = zi + snz[j];
        float d = fmaf(dx, dx, fmaf(dy, dy, dz * dz));
        if (d <= bound) { g_idx[base + cnt] = j; cnt++; }
    }
}

// ---------------- FPS: bit-exact vs reference ----------------
__global__ __launch_bounds__(256) void fps_kernel(const float* __restrict__ pos)
{
    int b = blockIdx.x, tid = threadIdx.x;
    __shared__ float sx[Np], sy[Np], sz[Np];
    __shared__ float wv[8]; __shared__ int wi[8];
    __shared__ int s_last;
    const float* p = pos + (size_t)b * Np * 3;
    for (int i = tid; i < Np; i += 256) { sx[i] = p[3*i]; sy[i] = p[3*i+1]; sz[i] = p[3*i+2]; }
    float dist[4];
#pragma unroll
    for (int q = 0; q < 4; q++) dist[q] = 1e38f;
    if (tid == 0) { g_fidx[b * Mf] = 0; s_last = 0; }
    __syncthreads();
    int last = 0;
    for (int step = 1; step < Mf; step++) {
        float lx = sx[last], ly = sy[last], lz = sz[last];
        float bv = -3.4e38f; int bix = 0x7fffffff;
#pragma unroll
        for (int q = 0; q < 4; q++) {
            int i = tid + q * 256;
            float dx = sx[i] - lx, dy = sy[i] - ly, dz = sz[i] - lz;
            float dd = __fadd_rn(__fadd_rn(__fmul_rn(dx,dx), __fmul_rn(dy,dy)), __fmul_rn(dz,dz));
            float nd = fminf(dist[q], dd);
            dist[q] = nd;
            if (nd > bv || (nd == bv && i < bix)) { bv = nd; bix = i; }
        }
#pragma unroll
        for (int o = 16; o > 0; o >>= 1) {
            float ov = __shfl_down_sync(0xffffffffu, bv, o);
            int   oi = __shfl_down_sync(0xffffffffu, bix, o);
            if (ov > bv || (ov == bv && oi < bix)) { bv = ov; bix = oi; }
        }
        if ((tid & 31) == 0) { wv[tid >> 5] = bv; wi[tid >> 5] = bix; }
        __syncthreads();
        if (tid == 0) {
            float v = wv[0]; int ix = wi[0];
#pragma unroll
            for (int w = 1; w < 8; w++)
                if (wv[w] > v || (wv[w] == v && wi[w] < ix)) { v = wv[w]; ix = wi[w]; }
            g_fidx[b * Mf + step] = ix; s_last = ix;
        }
        __syncthreads();
        last = s_last;
    }
}

// ---------------- BN1 statistics ----------------
__global__ __launch_bounds__(256) void stats1_kernel(const float* __restrict__ pos,
                                                     const float* __restrict__ w1,
                                                     const float* __restrict__ b1)
{
    __shared__ float rel[160][4];
    __shared__ float ssum[64], ssq[64];
    int tid = threadIdx.x;
    int p0  = blockIdx.x * 8;
    if (tid < 64) { ssum[tid] = 0.f; ssq[tid] = 0.f; }
    if (tid < 160) {
        int gp = p0 + tid / 20, k = tid % 20;
        int b  = gp >> 10;
        int nb = (b << 10) + g_idx[gp * Kn + k];
        rel[tid][0] = pos[nb*3+0] - pos[gp*3+0];
        rel[tid][1] = pos[nb*3+1] - pos[gp*3+1];
        rel[tid][2] = pos[nb*3+2] - pos[gp*3+2];
    }
    int c = tid & 63;
    float w0 = w1[c*3], wv1 = w1[c*3+1], wv2 = w1[c*3+2], bb = b1[c];
    __syncthreads();
    int rg = tid >> 6;
    float ps = 0.f, pq = 0.f;
#pragma unroll 4
    for (int q = 0; q < 40; q++) {
        int r = rg * 40 + q;
        float h = fmaf(rel[r][0], w0, fmaf(rel[r][1], wv1, fmaf(rel[r][2], wv2, bb)));
        h = fmaxf(h, 0.f);
        ps += h; pq = fmaf(h, h, pq);
    }
    atomicAdd(&ssum[c], ps); atomicAdd(&ssq[c], pq);
    __syncthreads();
    if (tid < 64) {
        g_part1[tid * NB1 + blockIdx.x]        = ssum[tid];
        g_part1[(64 + tid) * NB1 + blockIdx.x] = ssq[tid];
    }
}

// ---------------- two-stage reducers (stage A) ----------------
__global__ __launch_bounds__(256) void reduce1a_kernel()
{
    __shared__ double red[256];
    int row = blockIdx.x & 127, ch = blockIdx.x >> 7;   // 4 chunks of 2048
    int tid = threadIdx.x;
    double a = 0.0;
    int base = row * NB1 + ch * 2048;
#pragma unroll
    for (int t = 0; t < 8; t++) a += (double)g_part1[base + tid + t * 256];
    red[tid] = a; __syncthreads();
    for (int o = 128; o > 0; o >>= 1) { if (tid < o) red[tid] += red[tid + o]; __syncthreads(); }
    if (tid == 0) g_p1b[row * 4 + ch] = red[0];
}
__global__ __launch_bounds__(256) void reduce2a_kernel()
{
    __shared__ double red[256];
    int row = blockIdx.x & 127, ch = blockIdx.x >> 7;   // 8 chunks of 2048
    int tid = threadIdx.x;
    double a = 0.0;
    int base = row * NB2 + ch * 2048;
#pragma unroll
    for (int t = 0; t < 8; t++) a += (double)g_part2[base + tid + t * 256];
    red[tid] = a; __syncthreads();
    for (int o = 128; o > 0; o >>= 1) { if (tid < o) red[tid] += red[tid + o]; __syncthreads(); }
    if (tid == 0) g_p2b[row * 8 + ch] = red[0];
}

// ---------------- fold BN1 into W2/b2 (stage B merged) ----------------
__global__ __launch_bounds__(64) void fold1_kernel(const float* __restrict__ g1,
                                                   const float* __restrict__ be1,
                                                   const float* __restrict__ w2,
                                                   const float* __restrict__ b2)
{
    __shared__ float a1s[64], c1s[64];
    int t = threadIdx.x;
    const double CNT = (double)Bc * Np * Kn;
    double s = 0.0, q = 0.0;
#pragma unroll
    for (int ch = 0; ch < 4; ch++) { s += g_p1b[t * 4 + ch]; q += g_p1b[(64 + t) * 4 + ch]; }
    double m = s / CNT;
    double v = q / CNT - m * m;
    float af = g1[t] * (float)(1.0 / sqrt(v + (double)EPSf));
    a1s[t] = af;
    c1s[t] = be1[t] - (float)m * af;
    __syncthreads();
    float bb = b2[t];
    for (int f = 0; f < 64; f++) {
        float w = w2[t * 64 + f];
        g_W2p[t * 64 + f] = w * a1s[f];
        bb = fmaf(w, c1s[f], bb);
    }
    g_b2p[t] = bb;
}

// ---------------- main fused edge-MLP (f-pair packed FFMA2) ----------------
__global__ __launch_bounds__(256) void main_kernel(const float* __restrict__ pos,
                                                   const float* __restrict__ w1,
                                                   const float* __restrict__ b1)
{
    __shared__ __align__(16) float h1s[80 * 66];                 // stride 66 (even -> 8B aligned pairs)
    __shared__ __align__(16) unsigned long long w2pk[32 * 64];   // [fpair][g] packed (f even, f odd)
    __shared__ float rel[80][4];
    __shared__ float b2s[64];
    int tid = threadIdx.x;
#pragma unroll
    for (int t = 0; t < 8; t++) {
        int idx = tid + t * 256;            // 2048 entries
        int fp = idx >> 6, g = idx & 63;
        w2pk[fp * 64 + g] = *(const unsigned long long*)&g_W2p[g * 64 + 2 * fp];
    }
    if (tid < 64) b2s[tid] = g_b2p[tid];
    int p0 = blockIdx.x * 4;
    if (tid < 80) {
        int gp = p0 + tid / 20, k = tid % 20;
        int b  = gp >> 10;
        int nb = (b << 10) + g_idx[gp * Kn + k];
        rel[tid][0] = pos[nb*3+0] - pos[gp*3+0];
        rel[tid][1] = pos[nb*3+1] - pos[gp*3+1];
        rel[tid][2] = pos[nb*3+2] - pos[gp*3+2];
    }
    __syncthreads();
    {   // h1 = relu(rel @ W1^T + b1)
        int c = tid & 63, rg = tid >> 6;
        float w0 = w1[c*3], wv1 = w1[c*3+1], wv2 = w1[c*3+2], bb = b1[c];
#pragma unroll 4
        for (int q = 0; q < 20; q++) {
            int r = rg * 20 + q;
            float h = fmaf(rel[r][0], w0, fmaf(rel[r][1], wv1, fmaf(rel[r][2], wv2, bb)));
            h1s[r * 66 + c] = fmaxf(h, 0.f);
        }
    }
    __syncthreads();
    int cg = tid >> 4, rg2 = tid & 15;
    int r0 = rg2 * 5, c0 = cg * 4;
    unsigned long long acc[5][4];
#pragma unroll
    for (int i = 0; i < 5; i++)
#pragma unroll
        for (int j = 0; j < 4; j++) acc[i][j] = 0ull;
#pragma unroll 8
    for (int fp = 0; fp < 32; fp++) {
        ulonglong2 b01 = *(const ulonglong2*)&w2pk[fp * 64 + c0];
        ulonglong2 b23 = *(const ulonglong2*)&w2pk[fp * 64 + c0 + 2];
        int abase = r0 * 66 + 2 * fp;
#pragma unroll
        for (int i = 0; i < 5; i++) {
            unsigned long long ap = *(const unsigned long long*)&h1s[abase + 66 * i];
            acc[i][0] = ff2(ap, b01.x, acc[i][0]);
            acc[i][1] = ff2(ap, b01.y, acc[i][1]);
            acc[i][2] = ff2(ap, b23.x, acc[i][2]);
            acc[i][3] = ff2(ap, b23.y, acc[i][3]);
        }
    }
    // epilogue: combine even/odd halves, relu, per-point max/min + BN2 partial sums
    float bb0 = b2s[c0], bb1 = b2s[c0+1], bb2 = b2s[c0+2], bb3 = b2s[c0+3];
    float psum[4] = {0,0,0,0}, psq[4] = {0,0,0,0};
    float pmx[4], pmn[4];
#pragma unroll
    for (int j = 0; j < 4; j++) { pmx[j] = 0.f; pmn[j] = 3.4e38f; }
#pragma unroll
    for (int i = 0; i < 5; i++) {
        float lo, hi, v[4];
        upk2(acc[i][0], lo, hi); v[0] = fmaxf((lo + hi) + bb0, 0.f);
        upk2(acc[i][1], lo, hi); v[1] = fmaxf((lo + hi) + bb1, 0.f);
        upk2(acc[i][2], lo, hi); v[2] = fmaxf((lo + hi) + bb2, 0.f);
        upk2(acc[i][3], lo, hi); v[3] = fmaxf((lo + hi) + bb3, 0.f);
#pragma unroll
        for (int j = 0; j < 4; j++) {
            psum[j] += v[j]; psq[j] = fmaf(v[j], v[j], psq[j]);
            pmx[j] = fmaxf(pmx[j], v[j]); pmn[j] = fminf(pmn[j], v[j]);
        }
    }
    const unsigned FULL = 0xffffffffu;
#pragma unroll
    for (int o = 1; o <= 2; o <<= 1)
#pragma unroll
        for (int j = 0; j < 4; j++) {
            pmx[j] = fmaxf(pmx[j], __shfl_xor_sync(FULL, pmx[j], o));
            pmn[j] = fminf(pmn[j], __shfl_xor_sync(FULL, pmn[j], o));
        }
#pragma unroll
    for (int o = 1; o <= 8; o <<= 1)
#pragma unroll
        for (int j = 0; j < 4; j++) {
            psum[j] += __shfl_xor_sync(FULL, psum[j], o);
            psq[j]  += __shfl_xor_sync(FULL, psq[j],  o);
        }
    if ((tid & 3) == 0) {
        int pl = (tid >> 2) & 3;
        int gp = p0 + pl;
        *(float4*)&g_fmax[gp * 64 + c0] = make_float4(pmx[0], pmx[1], pmx[2], pmx[3]);
        *(float4*)&g_fmin[gp * 64 + c0] = make_float4(pmn[0], pmn[1], pmn[2], pmn[3]);
    }
    if ((tid & 15) == 0) {
#pragma unroll
        for (int j = 0; j < 4; j++) {
            g_part2[(c0 + j) * NB2 + blockIdx.x]      = psum[j];
            g_part2[(64 + c0 + j) * NB2 + blockIdx.x] = psq[j];
        }
    }
}

// ---------------- BN2 scale/shift (stage B merged) ----------------
__global__ __launch_bounds__(64) void bn2fold_kernel(const float* __restrict__ g2,
                                                     const float* __restrict__ be2)
{
    int c = threadIdx.x;
    const double CNT = (double)Bc * Np * Kn;
    double s = 0.0, q = 0.0;
#pragma unroll
    for (int ch = 0; ch < 8; ch++) { s += g_p2b[c * 8 + ch]; q += g_p2b[(64 + c) * 8 + ch]; }
    double m = s / CNT;
    double v = q / CNT - m * m;
    float sc = g2[c] * (float)(1.0 / sqrt(v + (double)EPSf));
    g_s2v[c] = sc;
    g_t2v[c] = be2[c] - (float)m * sc;
}

// ---------------- classifier ----------------
__global__ __launch_bounds__(128) void cls_kernel(const float* __restrict__ w_nn1,
                                                  const float* __restrict__ b_nn1)
{
    __shared__ __align__(16) float fs[32][64];
    __shared__ float s2s[64], t2s[64];
    int tid = threadIdx.x;
    int b = blockIdx.x >> 2, hc = blockIdx.x & 3;
    int h = hc * 128 + tid;
    if (tid < 64) { s2s[tid] = g_s2v[tid]; t2s[tid] = g_t2v[tid]; }
    __syncthreads();
    unsigned long long wrp[32];
    float beff = b_nn1[h];
#pragma unroll
    for (int c2 = 0; c2 < 32; c2++) {
        float wa = w_nn1[h * 64 + 2*c2], wb = w_nn1[h * 64 + 2*c2 + 1];
        beff = fmaf(wa, t2s[2*c2], beff);
        beff = fmaf(wb, t2s[2*c2 + 1], beff);
        wrp[c2] = pk2(wa * s2s[2*c2], wb * s2s[2*c2 + 1]);
    }
    float ymax = -3.4e38f;
    for (int mt = 0; mt < 8; mt++) {
        __syncthreads();
#pragma unroll
        for (int t = 0; t < 16; t++) {
            int l = tid + t * 128;
            int m = l >> 6, c = l & 63;
            int gi = g_fidx[b * Mf + mt * 32 + m];
            int gp = b * Np + gi;
            fs[m][c] = (s2s[c] > 0.f) ? g_fmax[gp * 64 + c] : g_fmin[gp * 64 + c];
        }
        __syncthreads();
        for (int m = 0; m < 32; m++) {
            unsigned long long acc = 0ull;
#pragma unroll
            for (int c4 = 0; c4 < 16; c4++) {
                ulonglong2 fv = *(const ulonglong2*)&fs[m][c4 * 4];
                acc = ff2(fv.x, wrp[2 * c4],     acc);
                acc = ff2(fv.y, wrp[2 * c4 + 1], acc);
            }
            float al, ah; upk2(acc, al, ah);
            ymax = fmaxf(ymax, (beff + al) + ah);
        }
    }
    g_ymax[b * 512 + h] = ymax;
}

// ---------------- head: relu + BN over batch ----------------
__global__ __launch_bounds__(128) void head_kernel(const float* __restrict__ gg,
                                                   const float* __restrict__ bb)
{
    int h = blockIdx.x * 128 + threadIdx.x;
    float s = 0.f, q = 0.f;
    for (int b = 0; b < Bc; b++) {
        float y = fmaxf(g_ymax[b * 512 + h], 0.f);
        s += y; q = fmaf(y, y, q);
    }
    float m  = s / 64.f;
    float v  = q / 64.f - m * m;
    float sc = gg[h] * rsqrtf(v + EPSf);
    float tt = bb[h] - m * sc;
    for (int b = 0; b < Bc; b++) {
        float y = fmaxf(g_ymax[b * 512 + h], 0.f);
        g_ybn[b * 512 + h] = fmaf(y, sc, tt);
    }
}

// ---------------- final linear + log_softmax ----------------
__global__ __launch_bounds__(64) void final_kernel(const float* __restrict__ w4,
                                                   const float* __restrict__ b4,
                                                   float* __restrict__ out)
{
    __shared__ float yr[512];
    __shared__ float lg[40];
    __shared__ float s_mx, s_lse;
    int b = blockIdx.x, tid = threadIdx.x;
#pragma unroll
    for (int t = 0; t < 8; t++) yr[tid + t * 64] = g_ybn[b * 512 + tid + t * 64];
    __syncthreads();
    if (tid < 40) {
        float acc = b4[tid];
        for (int c = 0; c < 512; c++) acc = fmaf(yr[c], w4[tid * 512 + c], acc);
        lg[tid] = acc;
    }
    __syncthreads();
    if (tid == 0) {
        float mx = -3.4e38f;
        for (int j = 0; j < 40; j++) mx = fmaxf(mx, lg[j]);
        float se = 0.f;
        for (int j = 0; j < 40; j++) se += expf(lg[j] - mx);
        s_mx = mx; s_lse = logf(se);
    }
    __syncthreads();
    if (tid < 40) out[b * 40 + tid] = lg[tid] - s_mx - s_lse;
}

// ---------------- launch (main_kernel placed 5th for ncu slot) ----------------
extern "C" void kernel_launch(void* const* d_in, const int* in_sizes, int n_in,
                              void* d_out, int out_size)
{
    const float* pos    = (const float*)d_in[0];
    const float* w1     = (const float*)d_in[1];
    const float* b1     = (const float*)d_in[2];
    const float* g1     = (const float*)d_in[3];
    const float* be1    = (const float*)d_in[4];
    const float* w2     = (const float*)d_in[5];
    const float* b2     = (const float*)d_in[6];
    const float* g2     = (const float*)d_in[7];
    const float* be2    = (const float*)d_in[8];
    const float* w_nn1  = (const float*)d_in[9];
    const float* b_nn1  = (const float*)d_in[10];
    const float* g_bn2  = (const float*)d_in[11];
    const float* be_bn2 = (const float*)d_in[12];
    const float* w_nn4  = (const float*)d_in[13];
    const float* b_nn4  = (const float*)d_in[14];
    float* out = (float*)d_out;

    knn_kernel    <<<256,  256>>>(pos);
    stats1_kernel <<<NB1,  256>>>(pos, w1, b1);
    reduce1a_kernel<<<512, 256>>>();
    fold1_kernel  <<<1,     64>>>(g1, be1, w2, b2);
    main_kernel   <<<NB2,  256>>>(pos, w1, b1);      // 5th launch -> profiled
    fps_kernel    <<<Bc,   256>>>(pos);
    reduce2a_kernel<<<1024,256>>>();
    bn2fold_kernel<<<1,     64>>>(g2, be2);
    cls_kernel    <<<256,  128>>>(w_nn1, b_nn1);
    head_kernel   <<<4,    128>>>(g_bn2, be_bn2);
    final_kernel  <<<Bc,    64>>>(w_nn4, b_nn4, out);
}